// round 1
// baseline (speedup 1.0000x reference)
#include <cuda_runtime.h>

#define Bv 4
#define Tv 2048
#define Cv 1024
#define Hv 16
#define HSv 64
#define MROWS (Bv * Tv)        // 8192
#define NQKV  (3 * Cv)         // 3072

// Scratch (device globals: allocation-guard-safe)
__device__ float g_qkv[(size_t)MROWS * NQKV];   // [B*T, 3C] ~100MB
__device__ float g_y[(size_t)MROWS * Cv];       // [B*T, C]  ~33MB

// ---------------------------------------------------------------------------
// Tiled fp32 GEMM: C[M,N] = A[M,K] @ B[K,N], all row-major.
// 64x64 block tile, BK=16, 256 threads, 4x4 per-thread microtile.
// A tile stored transposed in smem ([k][m]) so both fragments are LDS.128.
// Requires M%64==0, N%64==0, K%16==0 (true for all our shapes).
// ---------------------------------------------------------------------------
__global__ void __launch_bounds__(256) gemm_kernel(
    const float* __restrict__ A, const float* __restrict__ B,
    float* __restrict__ C, int M, int N, int K)
{
    __shared__ float Ast[16][64];   // [k][m]
    __shared__ float Bs[16][64];    // [k][n]

    const int bm = blockIdx.y * 64;
    const int bn = blockIdx.x * 64;
    const int tid = threadIdx.x;
    const int tx = tid & 15;        // 0..15
    const int ty = tid >> 4;        // 0..15

    // loader mapping
    const int a_row = tid >> 2;          // 0..63
    const int a_k4  = (tid & 3) * 4;     // 0,4,8,12
    const int b_row = tid >> 4;          // 0..15
    const int b_col = (tid & 15) * 4;    // 0..60

    float acc[4][4];
#pragma unroll
    for (int i = 0; i < 4; i++)
#pragma unroll
        for (int j = 0; j < 4; j++) acc[i][j] = 0.0f;

    for (int k0 = 0; k0 < K; k0 += 16) {
        // Load A tile (64x16), transpose into Ast
        float4 av = *(const float4*)&A[(size_t)(bm + a_row) * K + k0 + a_k4];
        Ast[a_k4 + 0][a_row] = av.x;
        Ast[a_k4 + 1][a_row] = av.y;
        Ast[a_k4 + 2][a_row] = av.z;
        Ast[a_k4 + 3][a_row] = av.w;
        // Load B tile (16x64), natural layout
        *(float4*)&Bs[b_row][b_col] =
            *(const float4*)&B[(size_t)(k0 + b_row) * N + bn + b_col];
        __syncthreads();

#pragma unroll
        for (int k = 0; k < 16; k++) {
            float4 af = *(const float4*)&Ast[k][ty * 4];
            float4 bf = *(const float4*)&Bs[k][tx * 4];
            float ar[4] = {af.x, af.y, af.z, af.w};
            float br[4] = {bf.x, bf.y, bf.z, bf.w};
#pragma unroll
            for (int i = 0; i < 4; i++)
#pragma unroll
                for (int j = 0; j < 4; j++)
                    acc[i][j] = fmaf(ar[i], br[j], acc[i][j]);
        }
        __syncthreads();
    }

#pragma unroll
    for (int i = 0; i < 4; i++) {
        float4 ov = make_float4(acc[i][0], acc[i][1], acc[i][2], acc[i][3]);
        *(float4*)&C[(size_t)(bm + ty * 4 + i) * N + bn + tx * 4] = ov;
    }
}

// ---------------------------------------------------------------------------
// Flash attention (causal), fp32. One CTA per (b*H+h, 64-query tile).
// Q,K tiles stored transposed [d][row] in smem (conflict-free LDS.128
// fragments); V natural [k][d]. P reuses K's smem (union) to fit 48KB static.
// Online softmax with 16-lane shuffle reductions (thread grid 16x16, 4x4 tile).
// ---------------------------------------------------------------------------
__global__ void __launch_bounds__(256) attn_kernel(
    const float* __restrict__ qkv, float* __restrict__ y)
{
    __shared__ float Qst[64][64];   // [d][q_row]
    __shared__ float KP[64][64];    // K: [d][k_col]; later P: [k][q_row]
    __shared__ float Vs[64][64];    // [k_row][d]

    const int qb = blockIdx.x;            // 0..31
    const int bh = blockIdx.y;            // 0..63
    const int b = bh / Hv;
    const int h = bh % Hv;

    const int tid = threadIdx.x;
    const int tx = tid & 15;
    const int ty = tid >> 4;

    const int l_row = tid >> 2;           // 0..63
    const int l_c4  = (tid & 3) * 4;      // 0,4,8,12

    const float scale = 0.125f;           // 1/sqrt(64)

    // ---- load Q tile transposed ----
    {
        const float* qbase = qkv + (size_t)(b * Tv + qb * 64) * NQKV + h * HSv;
#pragma unroll
        for (int i = 0; i < 4; i++) {
            int d0 = l_c4 + i * 16;
            float4 v = *(const float4*)&qbase[(size_t)l_row * NQKV + d0];
            Qst[d0 + 0][l_row] = v.x;
            Qst[d0 + 1][l_row] = v.y;
            Qst[d0 + 2][l_row] = v.z;
            Qst[d0 + 3][l_row] = v.w;
        }
    }

    float o[4][4];
    float m_r[4], l_r[4];
#pragma unroll
    for (int i = 0; i < 4; i++) {
        m_r[i] = -1e30f;
        l_r[i] = 0.0f;
#pragma unroll
        for (int j = 0; j < 4; j++) o[i][j] = 0.0f;
    }

    const int nkb = qb + 1;    // causal: only key blocks <= query block
    for (int jb = 0; jb < nkb; jb++) {
        __syncthreads();   // previous iter's KP/Vs reads complete (also orders Qst 1st iter)
        // ---- load K (transposed) and V (natural) tiles ----
        {
            const float* kbase = qkv + (size_t)(b * Tv + jb * 64) * NQKV + Cv + h * HSv;
            const float* vbase = qkv + (size_t)(b * Tv + jb * 64) * NQKV + 2 * Cv + h * HSv;
#pragma unroll
            for (int i = 0; i < 4; i++) {
                int d0 = l_c4 + i * 16;
                float4 kv = *(const float4*)&kbase[(size_t)l_row * NQKV + d0];
                KP[d0 + 0][l_row] = kv.x;
                KP[d0 + 1][l_row] = kv.y;
                KP[d0 + 2][l_row] = kv.z;
                KP[d0 + 3][l_row] = kv.w;
                *(float4*)&Vs[l_row][d0] = *(const float4*)&vbase[(size_t)l_row * NQKV + d0];
            }
        }
        __syncthreads();

        // ---- S = Q @ K^T (4x4 per thread) ----
        float s[4][4];
#pragma unroll
        for (int i = 0; i < 4; i++)
#pragma unroll
            for (int j = 0; j < 4; j++) s[i][j] = 0.0f;

#pragma unroll 8
        for (int d = 0; d < 64; d++) {
            float4 af = *(const float4*)&Qst[d][ty * 4];
            float4 bf = *(const float4*)&KP[d][tx * 4];
            float ar[4] = {af.x, af.y, af.z, af.w};
            float br[4] = {bf.x, bf.y, bf.z, bf.w};
#pragma unroll
            for (int i = 0; i < 4; i++)
#pragma unroll
                for (int j = 0; j < 4; j++)
                    s[i][j] = fmaf(ar[i], br[j], s[i][j]);
        }

        // ---- scale + causal mask (diagonal block only) ----
        const bool diag = (jb == qb);
#pragma unroll
        for (int i = 0; i < 4; i++)
#pragma unroll
            for (int j = 0; j < 4; j++) {
                float v = s[i][j] * scale;
                if (diag && (tx * 4 + j > ty * 4 + i)) v = -1e30f;
                s[i][j] = v;
            }

        // ---- online softmax (row reductions across 16 tx lanes) ----
#pragma unroll
        for (int i = 0; i < 4; i++) {
            float mx = fmaxf(fmaxf(s[i][0], s[i][1]), fmaxf(s[i][2], s[i][3]));
            mx = fmaxf(mx, __shfl_xor_sync(0xffffffffu, mx, 1, 16));
            mx = fmaxf(mx, __shfl_xor_sync(0xffffffffu, mx, 2, 16));
            mx = fmaxf(mx, __shfl_xor_sync(0xffffffffu, mx, 4, 16));
            mx = fmaxf(mx, __shfl_xor_sync(0xffffffffu, mx, 8, 16));
            float mnew = fmaxf(m_r[i], mx);
            float corr = __expf(m_r[i] - mnew);
            float rs = 0.0f;
#pragma unroll
            for (int j = 0; j < 4; j++) {
                float p = __expf(s[i][j] - mnew);
                s[i][j] = p;
                rs += p;
            }
            rs += __shfl_xor_sync(0xffffffffu, rs, 1, 16);
            rs += __shfl_xor_sync(0xffffffffu, rs, 2, 16);
            rs += __shfl_xor_sync(0xffffffffu, rs, 4, 16);
            rs += __shfl_xor_sync(0xffffffffu, rs, 8, 16);
            l_r[i] = l_r[i] * corr + rs;
            m_r[i] = mnew;
#pragma unroll
            for (int j = 0; j < 4; j++) o[i][j] *= corr;
        }

        __syncthreads();   // all K reads done before overwriting KP with P

        // ---- store P transposed: KP[k][q_row] ----
#pragma unroll
        for (int j = 0; j < 4; j++) {
            *(float4*)&KP[tx * 4 + j][ty * 4] =
                make_float4(s[0][j], s[1][j], s[2][j], s[3][j]);
        }
        __syncthreads();

        // ---- O += P @ V ----
#pragma unroll 8
        for (int k = 0; k < 64; k++) {
            float4 af = *(const float4*)&KP[k][ty * 4];
            float4 bf = *(const float4*)&Vs[k][tx * 4];
            float ar[4] = {af.x, af.y, af.z, af.w};
            float br[4] = {bf.x, bf.y, bf.z, bf.w};
#pragma unroll
            for (int i = 0; i < 4; i++)
#pragma unroll
                for (int j = 0; j < 4; j++)
                    o[i][j] = fmaf(ar[i], br[j], o[i][j]);
        }
    }

    // ---- epilogue: normalize + store y[b,t,h*64+d] ----
#pragma unroll
    for (int i = 0; i < 4; i++) {
        float inv = 1.0f / l_r[i];
        float4 ov = make_float4(o[i][0] * inv, o[i][1] * inv,
                                o[i][2] * inv, o[i][3] * inv);
        size_t row = (size_t)(b * Tv + qb * 64 + ty * 4 + i);
        *(float4*)&y[row * Cv + h * HSv + tx * 4] = ov;
    }
}

// ---------------------------------------------------------------------------
extern "C" void kernel_launch(void* const* d_in, const int* in_sizes, int n_in,
                              void* d_out, int out_size)
{
    const float* x      = (const float*)d_in[0];   // [4,2048,1024]
    const float* w_attn = (const float*)d_in[1];   // [1024,3072]
    const float* w_proj = (const float*)d_in[2];   // [1024,1024]
    float* out = (float*)d_out;                    // [4,2048,1024]

    void* p_qkv = nullptr;
    void* p_y = nullptr;
    cudaGetSymbolAddress(&p_qkv, g_qkv);
    cudaGetSymbolAddress(&p_y, g_y);
    float* qkv = (float*)p_qkv;
    float* y = (float*)p_y;

    dim3 blk(256);
    // qkv = x @ w_attn : [8192,3072]
    gemm_kernel<<<dim3(NQKV / 64, MROWS / 64), blk>>>(x, w_attn, qkv, MROWS, NQKV, Cv);
    // y = attention(qkv) : [8192,1024]
    attn_kernel<<<dim3(Tv / 64, Bv * Hv), blk>>>(qkv, y);
    // out = y @ w_proj : [8192,1024]
    gemm_kernel<<<dim3(Cv / 64, MROWS / 64), blk>>>(y, w_proj, out, MROWS, Cv, Cv);
}

// round 5
// speedup vs baseline: 1.5781x; 1.5781x over previous
#include <cuda_runtime.h>
#include <cuda_bf16.h>
#include <cstdint>

#define Bv 4
#define Tv 2048
#define Cv 1024
#define Hv 16
#define HSv 64
#define MROWS (Bv * Tv)        // 8192
#define NQKV  (3 * Cv)         // 3072

// ------------------------- device scratch (no allocs) -----------------------
__device__ float g_qkv[(size_t)MROWS * NQKV];          // [B*T, 3C] fp32
__device__ float g_y[(size_t)MROWS * Cv];              // [B*T, C]  fp32
__device__ __nv_bfloat16 g_xh[(size_t)MROWS * Cv];
__device__ __nv_bfloat16 g_xl[(size_t)MROWS * Cv];
__device__ __nv_bfloat16 g_yh[(size_t)MROWS * Cv];
__device__ __nv_bfloat16 g_yl[(size_t)MROWS * Cv];
__device__ __nv_bfloat16 g_wah[(size_t)NQKV * Cv];     // w_attn^T [3072,1024]
__device__ __nv_bfloat16 g_wal[(size_t)NQKV * Cv];
__device__ __nv_bfloat16 g_wph[(size_t)Cv * Cv];       // w_proj^T [1024,1024]
__device__ __nv_bfloat16 g_wpl[(size_t)Cv * Cv];

// ------------------------- PTX helpers (sm_103-base safe) --------------------
__device__ __forceinline__ uint32_t smem_u32(const void* p) {
    uint32_t a;
    asm("{ .reg .u64 t; cvta.to.shared.u64 t, %1; cvt.u32.u64 %0, t; }"
        : "=r"(a) : "l"(p));
    return a;
}
__device__ __forceinline__ void cp_async16(uint32_t dst, const void* src) {
    asm volatile("cp.async.cg.shared.global [%0], [%1], 16;"
                 :: "r"(dst), "l"(src) : "memory");
}
__device__ __forceinline__ void cp_commit() {
    asm volatile("cp.async.commit_group;" ::: "memory");
}
template <int N>
__device__ __forceinline__ void cp_wait() {
    asm volatile("cp.async.wait_group %0;" :: "n"(N) : "memory");
}
__device__ __forceinline__ void ldsm4(uint32_t* r, uint32_t addr) {
    asm volatile("ldmatrix.sync.aligned.m8n8.x4.shared.b16 {%0,%1,%2,%3}, [%4];"
                 : "=r"(r[0]), "=r"(r[1]), "=r"(r[2]), "=r"(r[3]) : "r"(addr));
}
__device__ __forceinline__ void mma_bf16(float* c, const uint32_t* a,
                                         uint32_t b0, uint32_t b1) {
    asm volatile(
        "mma.sync.aligned.m16n8k16.row.col.f32.bf16.bf16.f32 "
        "{%0,%1,%2,%3}, {%4,%5,%6,%7}, {%8,%9}, {%0,%1,%2,%3};"
        : "+f"(c[0]), "+f"(c[1]), "+f"(c[2]), "+f"(c[3])
        : "r"(a[0]), "r"(a[1]), "r"(a[2]), "r"(a[3]), "r"(b0), "r"(b1));
}

// ---------------------------------------------------------------------------
// Split fp32 -> (bf16 hi, bf16 lo)
// ---------------------------------------------------------------------------
__global__ void __launch_bounds__(256) split_kernel(
    const float* __restrict__ in, __nv_bfloat16* __restrict__ hi,
    __nv_bfloat16* __restrict__ lo, size_t n4)
{
    size_t i = (size_t)blockIdx.x * blockDim.x + threadIdx.x;
    size_t stride = (size_t)gridDim.x * blockDim.x;
    for (; i < n4; i += stride) {
        float4 v = ((const float4*)in)[i];
        __nv_bfloat16 h0 = __float2bfloat16(v.x);
        __nv_bfloat16 h1 = __float2bfloat16(v.y);
        __nv_bfloat16 h2 = __float2bfloat16(v.z);
        __nv_bfloat16 h3 = __float2bfloat16(v.w);
        __nv_bfloat16 l0 = __float2bfloat16(v.x - __bfloat162float(h0));
        __nv_bfloat16 l1 = __float2bfloat16(v.y - __bfloat162float(h1));
        __nv_bfloat16 l2 = __float2bfloat16(v.z - __bfloat162float(h2));
        __nv_bfloat16 l3 = __float2bfloat16(v.w - __bfloat162float(h3));
        ((__nv_bfloat162*)hi)[i * 2 + 0] = __nv_bfloat162(h0, h1);
        ((__nv_bfloat162*)hi)[i * 2 + 1] = __nv_bfloat162(h2, h3);
        ((__nv_bfloat162*)lo)[i * 2 + 0] = __nv_bfloat162(l0, l1);
        ((__nv_bfloat162*)lo)[i * 2 + 1] = __nv_bfloat162(l2, l3);
    }
}

// ---------------------------------------------------------------------------
// Transpose + split: w [K,N] fp32 -> hiT/loT [N,K] bf16
// ---------------------------------------------------------------------------
__global__ void __launch_bounds__(256) splitT_kernel(
    const float* __restrict__ w, __nv_bfloat16* __restrict__ hiT,
    __nv_bfloat16* __restrict__ loT, int K, int N)
{
    __shared__ float t[32][33];
    int n0 = blockIdx.x * 32;
    int k0 = blockIdx.y * 32;
    int tx = threadIdx.x & 31;
    int ty = threadIdx.x >> 5;
#pragma unroll
    for (int i = 0; i < 4; i++)
        t[ty + i * 8][tx] = w[(size_t)(k0 + ty + i * 8) * N + n0 + tx];
    __syncthreads();
#pragma unroll
    for (int i = 0; i < 4; i++) {
        float v = t[tx][ty + i * 8];
        __nv_bfloat16 h = __float2bfloat16(v);
        __nv_bfloat16 l = __float2bfloat16(v - __bfloat162float(h));
        size_t o = (size_t)(n0 + ty + i * 8) * K + k0 + tx;
        hiT[o] = h;
        loT[o] = l;
    }
}

// ---------------------------------------------------------------------------
// HMMA split-bf16 GEMM: C[M,N] = A[M,K] @ B[K,N], fp32-accurate (~1e-5).
// A as (Ah,Al) [M,K]; B as (Bh,Bl) [N,K] (pre-transposed = mma col-major).
// 128x128 CTA tile, BK=32, 8 warps (2M x 4N, warp tile 64x32),
// double-buffered cp.async, ldmatrix from 80B-padded rows (conflict-free).
// 3 passes: Ah*Bh + Ah*Bl + Al*Bh.
// ---------------------------------------------------------------------------
#define PADB 80                         // bytes per smem row (64 data + 16 pad)
#define PART_BYTES (128 * PADB)         // 10240
#define STAGE_BYTES (4 * PART_BYTES)    // 40960
#define GH_SMEM (2 * STAGE_BYTES)       // 81920

__global__ void __launch_bounds__(256) gemm_hmma_kernel(
    const __nv_bfloat16* __restrict__ Ah, const __nv_bfloat16* __restrict__ Al,
    const __nv_bfloat16* __restrict__ Bh, const __nv_bfloat16* __restrict__ Bl,
    float* __restrict__ C, int M, int N, int K)
{
    extern __shared__ char smem[];
    const uint32_t smem_base = smem_u32(smem);

    const int tid = threadIdx.x;
    const int wid = tid >> 5;
    const int lane = tid & 31;
    const int bm = blockIdx.y * 128;
    const int bn = blockIdx.x * 128;
    const int wm = (wid & 1) * 64;       // warp M offset in tile
    const int wn = (wid >> 1) * 32;      // warp N offset in tile

    float acc[4][4][4];
#pragma unroll
    for (int i = 0; i < 4; i++)
#pragma unroll
        for (int j = 0; j < 4; j++)
#pragma unroll
            for (int r = 0; r < 4; r++) acc[i][j][r] = 0.0f;

    const __nv_bfloat16* srcs[4] = {
        Ah + (size_t)bm * K, Al + (size_t)bm * K,
        Bh + (size_t)bn * K, Bl + (size_t)bn * K };

    const int nch = K >> 5;    // K/32

    // loader: per part, 512 16B-chunks / 256 threads = 2 each
    auto load_stage = [&](int kc) {
        const uint32_t sb = smem_base + (kc & 1) * STAGE_BYTES;
        const size_t koff = (size_t)kc << 5;
#pragma unroll
        for (int p = 0; p < 4; p++) {
#pragma unroll
            for (int r = 0; r < 2; r++) {
                int c = tid + r * 256;          // 0..511
                int row = c >> 2;
                int cn = c & 3;
                cp_async16(sb + p * PART_BYTES + row * PADB + cn * 16,
                           srcs[p] + (size_t)row * K + koff + cn * 8);
            }
        }
    };

    load_stage(0);
    cp_commit();

    // precomputed fragment address components
    const int arow_l = ((lane >> 3) & 1) * 8 + (lane & 7);
    const uint32_t acol_l = (uint32_t)((lane >> 4) * 16);
    const int brow_l = ((lane >> 4) << 3) + (lane & 7);
    const uint32_t bcol_l = (uint32_t)(((lane >> 3) & 1) * 16);

    for (int kc = 0; kc < nch; kc++) {
        if (kc + 1 < nch) {
            load_stage(kc + 1);
            cp_commit();
            cp_wait<1>();
        } else {
            cp_wait<0>();
        }
        __syncthreads();

        const uint32_t sb = smem_base + (kc & 1) * STAGE_BYTES;
        const uint32_t aH = sb, aL = sb + PART_BYTES;
        const uint32_t bH = sb + 2 * PART_BYTES, bL = sb + 3 * PART_BYTES;

#pragma unroll
        for (int s = 0; s < 2; s++) {
            uint32_t ah[4][4], al[4][4], bh[2][4], bl[2][4];
            const uint32_t ac = acol_l + s * 32;
            const uint32_t bc = bcol_l + s * 32;
#pragma unroll
            for (int i = 0; i < 4; i++) {
                uint32_t off = (uint32_t)((wm + i * 16 + arow_l) * PADB) + ac;
                ldsm4(ah[i], aH + off);
                ldsm4(al[i], aL + off);
            }
#pragma unroll
            for (int j = 0; j < 2; j++) {
                uint32_t off = (uint32_t)((wn + j * 16 + brow_l) * PADB) + bc;
                ldsm4(bh[j], bH + off);
                ldsm4(bl[j], bL + off);
            }
#pragma unroll
            for (int i = 0; i < 4; i++) {
#pragma unroll
                for (int j = 0; j < 2; j++) {
                    mma_bf16(acc[i][2 * j],     ah[i], bh[j][0], bh[j][1]);
                    mma_bf16(acc[i][2 * j + 1], ah[i], bh[j][2], bh[j][3]);
                    mma_bf16(acc[i][2 * j],     ah[i], bl[j][0], bl[j][1]);
                    mma_bf16(acc[i][2 * j + 1], ah[i], bl[j][2], bl[j][3]);
                    mma_bf16(acc[i][2 * j],     al[i], bh[j][0], bh[j][1]);
                    mma_bf16(acc[i][2 * j + 1], al[i], bh[j][2], bh[j][3]);
                }
            }
        }
        __syncthreads();
    }

    // epilogue: each lane owns rows (l/4, l/4+8) cols 2*(l%4)+{0,1} per tile
    const int erow = lane >> 2;
    const int ecol = (lane & 3) * 2;
#pragma unroll
    for (int i = 0; i < 4; i++) {
#pragma unroll
        for (int j = 0; j < 4; j++) {
            size_t r0 = (size_t)(bm + wm + i * 16 + erow);
            int c = bn + wn + j * 8 + ecol;
            *(float2*)&C[r0 * N + c] = make_float2(acc[i][j][0], acc[i][j][1]);
            *(float2*)&C[(r0 + 8) * N + c] = make_float2(acc[i][j][2], acc[i][j][3]);
        }
    }
}

// ---------------------------------------------------------------------------
// Flash attention (causal), fp32 — unchanged (passing, rel_err 1.2e-6).
// ---------------------------------------------------------------------------
__global__ void __launch_bounds__(256) attn_kernel(
    const float* __restrict__ qkv, float* __restrict__ y)
{
    __shared__ float Qst[64][64];
    __shared__ float KP[64][64];
    __shared__ float Vs[64][64];

    const int qb = blockIdx.x;
    const int bh = blockIdx.y;
    const int b = bh / Hv;
    const int h = bh % Hv;

    const int tid = threadIdx.x;
    const int tx = tid & 15;
    const int ty = tid >> 4;
    const int l_row = tid >> 2;
    const int l_c4  = (tid & 3) * 4;
    const float scale = 0.125f;

    {
        const float* qbase = qkv + (size_t)(b * Tv + qb * 64) * NQKV + h * HSv;
#pragma unroll
        for (int i = 0; i < 4; i++) {
            int d0 = l_c4 + i * 16;
            float4 v = *(const float4*)&qbase[(size_t)l_row * NQKV + d0];
            Qst[d0 + 0][l_row] = v.x;
            Qst[d0 + 1][l_row] = v.y;
            Qst[d0 + 2][l_row] = v.z;
            Qst[d0 + 3][l_row] = v.w;
        }
    }

    float o[4][4];
    float m_r[4], l_r[4];
#pragma unroll
    for (int i = 0; i < 4; i++) {
        m_r[i] = -1e30f;
        l_r[i] = 0.0f;
#pragma unroll
        for (int j = 0; j < 4; j++) o[i][j] = 0.0f;
    }

    const int nkb = qb + 1;
    for (int jb = 0; jb < nkb; jb++) {
        __syncthreads();
        {
            const float* kbase = qkv + (size_t)(b * Tv + jb * 64) * NQKV + Cv + h * HSv;
            const float* vbase = qkv + (size_t)(b * Tv + jb * 64) * NQKV + 2 * Cv + h * HSv;
#pragma unroll
            for (int i = 0; i < 4; i++) {
                int d0 = l_c4 + i * 16;
                float4 kv = *(const float4*)&kbase[(size_t)l_row * NQKV + d0];
                KP[d0 + 0][l_row] = kv.x;
                KP[d0 + 1][l_row] = kv.y;
                KP[d0 + 2][l_row] = kv.z;
                KP[d0 + 3][l_row] = kv.w;
                *(float4*)&Vs[l_row][d0] = *(const float4*)&vbase[(size_t)l_row * NQKV + d0];
            }
        }
        __syncthreads();

        float s[4][4];
#pragma unroll
        for (int i = 0; i < 4; i++)
#pragma unroll
            for (int j = 0; j < 4; j++) s[i][j] = 0.0f;

#pragma unroll 8
        for (int d = 0; d < 64; d++) {
            float4 af = *(const float4*)&Qst[d][ty * 4];
            float4 bf = *(const float4*)&KP[d][tx * 4];
            float ar[4] = {af.x, af.y, af.z, af.w};
            float br[4] = {bf.x, bf.y, bf.z, bf.w};
#pragma unroll
            for (int i = 0; i < 4; i++)
#pragma unroll
                for (int j = 0; j < 4; j++)
                    s[i][j] = fmaf(ar[i], br[j], s[i][j]);
        }

        const bool diag = (jb == qb);
#pragma unroll
        for (int i = 0; i < 4; i++)
#pragma unroll
            for (int j = 0; j < 4; j++) {
                float v = s[i][j] * scale;
                if (diag && (tx * 4 + j > ty * 4 + i)) v = -1e30f;
                s[i][j] = v;
            }

#pragma unroll
        for (int i = 0; i < 4; i++) {
            float mx = fmaxf(fmaxf(s[i][0], s[i][1]), fmaxf(s[i][2], s[i][3]));
            mx = fmaxf(mx, __shfl_xor_sync(0xffffffffu, mx, 1, 16));
            mx = fmaxf(mx, __shfl_xor_sync(0xffffffffu, mx, 2, 16));
            mx = fmaxf(mx, __shfl_xor_sync(0xffffffffu, mx, 4, 16));
            mx = fmaxf(mx, __shfl_xor_sync(0xffffffffu, mx, 8, 16));
            float mnew = fmaxf(m_r[i], mx);
            float corr = __expf(m_r[i] - mnew);
            float rs = 0.0f;
#pragma unroll
            for (int j = 0; j < 4; j++) {
                float p = __expf(s[i][j] - mnew);
                s[i][j] = p;
                rs += p;
            }
            rs += __shfl_xor_sync(0xffffffffu, rs, 1, 16);
            rs += __shfl_xor_sync(0xffffffffu, rs, 2, 16);
            rs += __shfl_xor_sync(0xffffffffu, rs, 4, 16);
            rs += __shfl_xor_sync(0xffffffffu, rs, 8, 16);
            l_r[i] = l_r[i] * corr + rs;
            m_r[i] = mnew;
#pragma unroll
            for (int j = 0; j < 4; j++) o[i][j] *= corr;
        }

        __syncthreads();

#pragma unroll
        for (int j = 0; j < 4; j++) {
            *(float4*)&KP[tx * 4 + j][ty * 4] =
                make_float4(s[0][j], s[1][j], s[2][j], s[3][j]);
        }
        __syncthreads();

#pragma unroll 8
        for (int k = 0; k < 64; k++) {
            float4 af = *(const float4*)&KP[k][ty * 4];
            float4 bf = *(const float4*)&Vs[k][tx * 4];
            float ar[4] = {af.x, af.y, af.z, af.w};
            float br[4] = {bf.x, bf.y, bf.z, bf.w};
#pragma unroll
            for (int i = 0; i < 4; i++)
#pragma unroll
                for (int j = 0; j < 4; j++)
                    o[i][j] = fmaf(ar[i], br[j], o[i][j]);
        }
    }

#pragma unroll
    for (int i = 0; i < 4; i++) {
        float inv = 1.0f / l_r[i];
        float4 ov = make_float4(o[i][0] * inv, o[i][1] * inv,
                                o[i][2] * inv, o[i][3] * inv);
        size_t row = (size_t)(b * Tv + qb * 64 + ty * 4 + i);
        *(float4*)&y[row * Cv + h * HSv + tx * 4] = ov;
    }
}

// ---------------------------------------------------------------------------
extern "C" void kernel_launch(void* const* d_in, const int* in_sizes, int n_in,
                              void* d_out, int out_size)
{
    const float* x      = (const float*)d_in[0];   // [4,2048,1024]
    const float* w_attn = (const float*)d_in[1];   // [1024,3072]
    const float* w_proj = (const float*)d_in[2];   // [1024,1024]
    float* out = (float*)d_out;                    // [4,2048,1024]

    void *p_qkv, *p_y, *p_xh, *p_xl, *p_yh, *p_yl, *p_wah, *p_wal, *p_wph, *p_wpl;
    cudaGetSymbolAddress(&p_qkv, g_qkv);
    cudaGetSymbolAddress(&p_y, g_y);
    cudaGetSymbolAddress(&p_xh, g_xh);
    cudaGetSymbolAddress(&p_xl, g_xl);
    cudaGetSymbolAddress(&p_yh, g_yh);
    cudaGetSymbolAddress(&p_yl, g_yl);
    cudaGetSymbolAddress(&p_wah, g_wah);
    cudaGetSymbolAddress(&p_wal, g_wal);
    cudaGetSymbolAddress(&p_wph, g_wph);
    cudaGetSymbolAddress(&p_wpl, g_wpl);

    cudaFuncSetAttribute(gemm_hmma_kernel,
                         cudaFuncAttributeMaxDynamicSharedMemorySize, GH_SMEM);

    // 1. split x into bf16 hi/lo
    split_kernel<<<1024, 256>>>(x, (__nv_bfloat16*)p_xh, (__nv_bfloat16*)p_xl,
                                (size_t)MROWS * Cv / 4);
    // 2. transpose+split weights
    splitT_kernel<<<dim3(NQKV / 32, Cv / 32), 256>>>(
        w_attn, (__nv_bfloat16*)p_wah, (__nv_bfloat16*)p_wal, Cv, NQKV);
    splitT_kernel<<<dim3(Cv / 32, Cv / 32), 256>>>(
        w_proj, (__nv_bfloat16*)p_wph, (__nv_bfloat16*)p_wpl, Cv, Cv);

    // 3. qkv = x @ w_attn
    gemm_hmma_kernel<<<dim3(NQKV / 128, MROWS / 128), 256, GH_SMEM>>>(
        (const __nv_bfloat16*)p_xh, (const __nv_bfloat16*)p_xl,
        (const __nv_bfloat16*)p_wah, (const __nv_bfloat16*)p_wal,
        (float*)p_qkv, MROWS, NQKV, Cv);

    // 4. attention
    attn_kernel<<<dim3(Tv / 64, Bv * Hv), 256>>>((const float*)p_qkv, (float*)p_y);

    // 5. split y
    split_kernel<<<1024, 256>>>((const float*)p_y, (__nv_bfloat16*)p_yh,
                                (__nv_bfloat16*)p_yl, (size_t)MROWS * Cv / 4);

    // 6. out = y @ w_proj
    gemm_hmma_kernel<<<dim3(Cv / 128, MROWS / 128), 256, GH_SMEM>>>(
        (const __nv_bfloat16*)p_yh, (const __nv_bfloat16*)p_yl,
        (const __nv_bfloat16*)p_wph, (const __nv_bfloat16*)p_wpl,
        out, MROWS, Cv, Cv);
}

// round 9
// speedup vs baseline: 3.1007x; 1.9648x over previous
#include <cuda_runtime.h>
#include <cuda_bf16.h>
#include <cstdint>

#define Bv 4
#define Tv 2048
#define Cv 1024
#define Hv 16
#define HSv 64
#define MROWS (Bv * Tv)        // 8192
#define NQKV  (3 * Cv)         // 3072

// ------------------------- device scratch (no allocs) -----------------------
__device__ __nv_bfloat16 g_qkvh[(size_t)MROWS * NQKV]; // qkv split hi [8192,3072]
__device__ __nv_bfloat16 g_qkvl[(size_t)MROWS * NQKV];
__device__ __nv_bfloat16 g_xh[(size_t)MROWS * Cv];
__device__ __nv_bfloat16 g_xl[(size_t)MROWS * Cv];
__device__ __nv_bfloat16 g_yh[(size_t)MROWS * Cv];
__device__ __nv_bfloat16 g_yl[(size_t)MROWS * Cv];
__device__ __nv_bfloat16 g_wah[(size_t)NQKV * Cv];     // w_attn^T [3072,1024]
__device__ __nv_bfloat16 g_wal[(size_t)NQKV * Cv];
__device__ __nv_bfloat16 g_wph[(size_t)Cv * Cv];       // w_proj^T [1024,1024]
__device__ __nv_bfloat16 g_wpl[(size_t)Cv * Cv];

// ------------------------- PTX helpers (sm_103-base safe) --------------------
__device__ __forceinline__ uint32_t smem_u32(const void* p) {
    uint32_t a;
    asm("{ .reg .u64 t; cvta.to.shared.u64 t, %1; cvt.u32.u64 %0, t; }"
        : "=r"(a) : "l"(p));
    return a;
}
__device__ __forceinline__ void cp_async16(uint32_t dst, const void* src) {
    asm volatile("cp.async.cg.shared.global [%0], [%1], 16;"
                 :: "r"(dst), "l"(src) : "memory");
}
__device__ __forceinline__ void cp_commit() {
    asm volatile("cp.async.commit_group;" ::: "memory");
}
template <int N>
__device__ __forceinline__ void cp_wait() {
    asm volatile("cp.async.wait_group %0;" :: "n"(N) : "memory");
}
__device__ __forceinline__ void ldsm4(uint32_t* r, uint32_t addr) {
    asm volatile("ldmatrix.sync.aligned.m8n8.x4.shared.b16 {%0,%1,%2,%3}, [%4];"
                 : "=r"(r[0]), "=r"(r[1]), "=r"(r[2]), "=r"(r[3]) : "r"(addr));
}
__device__ __forceinline__ void ldsm4t(uint32_t* r, uint32_t addr) {
    asm volatile("ldmatrix.sync.aligned.m8n8.x4.trans.shared.b16 {%0,%1,%2,%3}, [%4];"
                 : "=r"(r[0]), "=r"(r[1]), "=r"(r[2]), "=r"(r[3]) : "r"(addr));
}
__device__ __forceinline__ void mma_bf16(float* c, const uint32_t* a,
                                         uint32_t b0, uint32_t b1) {
    asm volatile(
        "mma.sync.aligned.m16n8k16.row.col.f32.bf16.bf16.f32 "
        "{%0,%1,%2,%3}, {%4,%5,%6,%7}, {%8,%9}, {%0,%1,%2,%3};"
        : "+f"(c[0]), "+f"(c[1]), "+f"(c[2]), "+f"(c[3])
        : "r"(a[0]), "r"(a[1]), "r"(a[2]), "r"(a[3]), "r"(b0), "r"(b1));
}
// split two fp32 into packed bf16 hi-pair and lo-pair (elem0 in low half)
__device__ __forceinline__ void split_pack2(float v0, float v1,
                                            uint32_t& h, uint32_t& l) {
    __nv_bfloat16 h0 = __float2bfloat16(v0);
    __nv_bfloat16 h1 = __float2bfloat16(v1);
    __nv_bfloat16 l0 = __float2bfloat16(v0 - __bfloat162float(h0));
    __nv_bfloat16 l1 = __float2bfloat16(v1 - __bfloat162float(h1));
    __nv_bfloat162 hh(h0, h1), ll(l0, l1);
    h = *(uint32_t*)&hh;
    l = *(uint32_t*)&ll;
}

// ---------------------------------------------------------------------------
// Split fp32 -> (bf16 hi, bf16 lo)
// ---------------------------------------------------------------------------
__global__ void __launch_bounds__(256) split_kernel(
    const float* __restrict__ in, __nv_bfloat16* __restrict__ hi,
    __nv_bfloat16* __restrict__ lo, size_t n4)
{
    size_t i = (size_t)blockIdx.x * blockDim.x + threadIdx.x;
    size_t stride = (size_t)gridDim.x * blockDim.x;
    for (; i < n4; i += stride) {
        float4 v = ((const float4*)in)[i];
        uint32_t h01, l01, h23, l23;
        split_pack2(v.x, v.y, h01, l01);
        split_pack2(v.z, v.w, h23, l23);
        ((uint32_t*)hi)[i * 2 + 0] = h01;
        ((uint32_t*)hi)[i * 2 + 1] = h23;
        ((uint32_t*)lo)[i * 2 + 0] = l01;
        ((uint32_t*)lo)[i * 2 + 1] = l23;
    }
}

// ---------------------------------------------------------------------------
// Transpose + split: w [K,N] fp32 -> hiT/loT [N,K] bf16
// ---------------------------------------------------------------------------
__global__ void __launch_bounds__(256) splitT_kernel(
    const float* __restrict__ w, __nv_bfloat16* __restrict__ hiT,
    __nv_bfloat16* __restrict__ loT, int K, int N)
{
    __shared__ float t[32][33];
    int n0 = blockIdx.x * 32;
    int k0 = blockIdx.y * 32;
    int tx = threadIdx.x & 31;
    int ty = threadIdx.x >> 5;
#pragma unroll
    for (int i = 0; i < 4; i++)
        t[ty + i * 8][tx] = w[(size_t)(k0 + ty + i * 8) * N + n0 + tx];
    __syncthreads();
#pragma unroll
    for (int i = 0; i < 4; i++) {
        float v = t[tx][ty + i * 8];
        __nv_bfloat16 h = __float2bfloat16(v);
        __nv_bfloat16 l = __float2bfloat16(v - __bfloat162float(h));
        size_t o = (size_t)(n0 + ty + i * 8) * K + k0 + tx;
        hiT[o] = h;
        loT[o] = l;
    }
}

// ---------------------------------------------------------------------------
// HMMA split-bf16 GEMM: C[M,N] = A[M,K] @ B[K,N], fp32-accurate (~1e-5).
// SPLIT=true: write Ch/Cl bf16 pair outputs. SPLIT=false: write fp32 C.
// 128x128 CTA tile, BK=32, 8 warps (2Mx4N), double-buffered cp.async,
// __launch_bounds__(256,2): 2 CTAs/SM (regs<=128, smem 2x80KB).
// ---------------------------------------------------------------------------
#define PADB 80
#define PART_BYTES (128 * PADB)
#define STAGE_BYTES (4 * PART_BYTES)
#define GH_SMEM (2 * STAGE_BYTES)       // 81920

template <bool SPLIT>
__global__ void __launch_bounds__(256, 2) gemm_hmma_kernel(
    const __nv_bfloat16* __restrict__ Ah, const __nv_bfloat16* __restrict__ Al,
    const __nv_bfloat16* __restrict__ Bh, const __nv_bfloat16* __restrict__ Bl,
    float* __restrict__ C, __nv_bfloat16* __restrict__ Ch,
    __nv_bfloat16* __restrict__ Cl, int M, int N, int K)
{
    extern __shared__ char smem[];
    const uint32_t smem_base = smem_u32(smem);

    const int tid = threadIdx.x;
    const int wid = tid >> 5;
    const int lane = tid & 31;
    const int bm = blockIdx.y * 128;
    const int bn = blockIdx.x * 128;
    const int wm = (wid & 1) * 64;
    const int wn = (wid >> 1) * 32;

    float acc[4][4][4];
#pragma unroll
    for (int i = 0; i < 4; i++)
#pragma unroll
        for (int j = 0; j < 4; j++)
#pragma unroll
            for (int r = 0; r < 4; r++) acc[i][j][r] = 0.0f;

    const __nv_bfloat16* srcs[4] = {
        Ah + (size_t)bm * K, Al + (size_t)bm * K,
        Bh + (size_t)bn * K, Bl + (size_t)bn * K };

    const int nch = K >> 5;

    auto load_stage = [&](int kc) {
        const uint32_t sb = smem_base + (kc & 1) * STAGE_BYTES;
        const size_t koff = (size_t)kc << 5;
#pragma unroll
        for (int p = 0; p < 4; p++) {
#pragma unroll
            for (int r = 0; r < 2; r++) {
                int c = tid + r * 256;
                int row = c >> 2;
                int cn = c & 3;
                cp_async16(sb + p * PART_BYTES + row * PADB + cn * 16,
                           srcs[p] + (size_t)row * K + koff + cn * 8);
            }
        }
    };

    load_stage(0);
    cp_commit();

    const int arow_l = ((lane >> 3) & 1) * 8 + (lane & 7);
    const uint32_t acol_l = (uint32_t)((lane >> 4) * 16);
    const int brow_l = ((lane >> 4) << 3) + (lane & 7);
    const uint32_t bcol_l = (uint32_t)(((lane >> 3) & 1) * 16);

    for (int kc = 0; kc < nch; kc++) {
        if (kc + 1 < nch) {
            load_stage(kc + 1);
            cp_commit();
            cp_wait<1>();
        } else {
            cp_wait<0>();
        }
        __syncthreads();

        const uint32_t sb = smem_base + (kc & 1) * STAGE_BYTES;
        const uint32_t aH = sb, aL = sb + PART_BYTES;
        const uint32_t bH = sb + 2 * PART_BYTES, bL = sb + 3 * PART_BYTES;

#pragma unroll
        for (int s = 0; s < 2; s++) {
            uint32_t ah[4][4], al[4][4], bh[2][4], bl[2][4];
            const uint32_t ac = acol_l + s * 32;
            const uint32_t bc = bcol_l + s * 32;
#pragma unroll
            for (int i = 0; i < 4; i++) {
                uint32_t off = (uint32_t)((wm + i * 16 + arow_l) * PADB) + ac;
                ldsm4(ah[i], aH + off);
                ldsm4(al[i], aL + off);
            }
#pragma unroll
            for (int j = 0; j < 2; j++) {
                uint32_t off = (uint32_t)((wn + j * 16 + brow_l) * PADB) + bc;
                ldsm4(bh[j], bH + off);
                ldsm4(bl[j], bL + off);
            }
#pragma unroll
            for (int i = 0; i < 4; i++) {
#pragma unroll
                for (int j = 0; j < 2; j++) {
                    mma_bf16(acc[i][2 * j],     ah[i], bh[j][0], bh[j][1]);
                    mma_bf16(acc[i][2 * j + 1], ah[i], bh[j][2], bh[j][3]);
                    mma_bf16(acc[i][2 * j],     ah[i], bl[j][0], bl[j][1]);
                    mma_bf16(acc[i][2 * j + 1], ah[i], bl[j][2], bl[j][3]);
                    mma_bf16(acc[i][2 * j],     al[i], bh[j][0], bh[j][1]);
                    mma_bf16(acc[i][2 * j + 1], al[i], bh[j][2], bh[j][3]);
                }
            }
        }
        __syncthreads();
    }

    const int erow = lane >> 2;
    const int ecol = (lane & 3) * 2;
#pragma unroll
    for (int i = 0; i < 4; i++) {
#pragma unroll
        for (int j = 0; j < 4; j++) {
            size_t r0 = (size_t)(bm + wm + i * 16 + erow);
            int c = bn + wn + j * 8 + ecol;
            if (SPLIT) {
                uint32_t h01, l01, h23, l23;
                split_pack2(acc[i][j][0], acc[i][j][1], h01, l01);
                split_pack2(acc[i][j][2], acc[i][j][3], h23, l23);
                ((uint32_t*)Ch)[(r0 * N + c) >> 1] = h01;
                ((uint32_t*)Cl)[(r0 * N + c) >> 1] = l01;
                ((uint32_t*)Ch)[((r0 + 8) * N + c) >> 1] = h23;
                ((uint32_t*)Cl)[((r0 + 8) * N + c) >> 1] = l23;
            } else {
                *(float2*)&C[r0 * N + c] = make_float2(acc[i][j][0], acc[i][j][1]);
                *(float2*)&C[(r0 + 8) * N + c] = make_float2(acc[i][j][2], acc[i][j][3]);
            }
        }
    }
}

// ---------------------------------------------------------------------------
// Tensor-core flash attention (causal), split-bf16 3-pass, fp32-accurate.
// CTA: (b,h) x 128-query block; 8 warps, each owns 16 query rows.
// S = QhKh + QhKl + QlKh (fp32 acc); P split in-register; O = PhVh+PhVl+PlVh.
// K/V double-buffered via cp.async; V B-frags via ldmatrix.trans.
// Writes yh/yl bf16 directly.
// ---------------------------------------------------------------------------
#define AT_RS 144                        // smem row stride bytes (128 data + 16)
#define AT_PART (128 * AT_RS)            // 18432
#define AT_QH 0
#define AT_QL AT_PART
#define AT_KV0 (2 * AT_PART)
#define AT_BUF (4 * AT_PART)
#define AT_SMEM (2 * AT_PART + 2 * AT_BUF)   // 184320

__global__ void __launch_bounds__(256) attn_tc_kernel(
    const __nv_bfloat16* __restrict__ qkvh,
    const __nv_bfloat16* __restrict__ qkvl,
    __nv_bfloat16* __restrict__ yh, __nv_bfloat16* __restrict__ yl)
{
    extern __shared__ char smem[];
    const uint32_t sb = smem_u32(smem);
    const int tid = threadIdx.x;
    const int wid = tid >> 5;
    const int lane = tid & 31;
    const int qb = (int)gridDim.x - 1 - (int)blockIdx.x;   // heavy CTAs first
    const int bh = blockIdx.y;
    const int b = bh >> 4;
    const int h = bh & 15;
    const int coff = h * HSv;

    // ---- Q tile cp.async (hi+lo) ----
    {
        const size_t qrow0 = (size_t)b * Tv + qb * 128;
        const __nv_bfloat16* s2[2] = { qkvh, qkvl };
#pragma unroll
        for (int p = 0; p < 2; p++)
#pragma unroll
            for (int i = 0; i < 4; i++) {
                int c = tid + i * 256;
                int row = c >> 3, cn = c & 7;
                cp_async16(sb + (p ? AT_QL : AT_QH) + row * AT_RS + cn * 16,
                           s2[p] + (qrow0 + row) * NQKV + coff + cn * 8);
            }
    }
    auto load_kv = [&](int kb) {
        const uint32_t base = sb + AT_KV0 + (kb & 1) * AT_BUF;
        const size_t krow0 = (size_t)b * Tv + kb * 128;
        const __nv_bfloat16* s4[4] = { qkvh + Cv, qkvl + Cv,
                                       qkvh + 2 * Cv, qkvl + 2 * Cv };
#pragma unroll
        for (int p = 0; p < 4; p++)
#pragma unroll
            for (int i = 0; i < 4; i++) {
                int c = tid + i * 256;
                int row = c >> 3, cn = c & 7;
                cp_async16(base + p * AT_PART + row * AT_RS + cn * 16,
                           s4[p] + (krow0 + row) * NQKV + coff + cn * 8);
            }
    };
    load_kv(0);
    cp_commit();
    cp_wait<0>();
    __syncthreads();

    // ---- Q fragments (cached for all kblocks) ----
    const int arow = ((lane >> 3) & 1) * 8 + (lane & 7);
    const uint32_t acol = (uint32_t)((lane >> 4) * 16);
    const int wq = wid * 16;
    uint32_t qh[4][4], ql[4][4];
#pragma unroll
    for (int t = 0; t < 4; t++) {
        uint32_t off = (uint32_t)((wq + arow) * AT_RS) + acol + t * 32;
        ldsm4(qh[t], sb + AT_QH + off);
        ldsm4(ql[t], sb + AT_QL + off);
    }

    const int brow = ((lane >> 4) << 3) + (lane & 7);
    const uint32_t bcol = (uint32_t)(((lane >> 3) & 1) * 16);
    const int vrow = (((lane >> 3) & 1) << 3) + (lane & 7);
    const uint32_t vcol = (uint32_t)((lane >> 4) * 16);

    float oacc[8][4];
#pragma unroll
    for (int e = 0; e < 8; e++)
#pragma unroll
        for (int r = 0; r < 4; r++) oacc[e][r] = 0.0f;
    float m0 = -1e30f, m1 = -1e30f, l0 = 0.0f, l1 = 0.0f;
    const int r0 = lane >> 2;
    const int cpair = (lane & 3) * 2;
    const int qi0 = qb * 128 + wq + r0;
    const int qi1 = qi0 + 8;

    for (int kb = 0; kb <= qb; kb++) {
        const bool have_next = (kb < qb);
        if (have_next) { load_kv(kb + 1); cp_commit(); }
        const uint32_t kvb = sb + AT_KV0 + (kb & 1) * AT_BUF;
        const uint32_t KH = kvb, KL = kvb + AT_PART;
        const uint32_t VH = kvb + 2 * AT_PART, VL = kvb + 3 * AT_PART;

        // ---- S = Q @ K^T (3-pass) ----
        float sacc[16][4];
#pragma unroll
        for (int j = 0; j < 16; j++)
#pragma unroll
            for (int r = 0; r < 4; r++) sacc[j][r] = 0.0f;

#pragma unroll
        for (int g = 0; g < 8; g++) {
#pragma unroll
            for (int t = 0; t < 4; t++) {
                uint32_t off = (uint32_t)((g * 16 + brow) * AT_RS) + bcol + t * 32;
                uint32_t kh[4], kl[4];
                ldsm4(kh, KH + off);
                ldsm4(kl, KL + off);
                mma_bf16(sacc[2 * g],     qh[t], kh[0], kh[1]);
                mma_bf16(sacc[2 * g + 1], qh[t], kh[2], kh[3]);
                mma_bf16(sacc[2 * g],     qh[t], kl[0], kl[1]);
                mma_bf16(sacc[2 * g + 1], qh[t], kl[2], kl[3]);
                mma_bf16(sacc[2 * g],     ql[t], kh[0], kh[1]);
                mma_bf16(sacc[2 * g + 1], ql[t], kh[2], kh[3]);
            }
        }

        // ---- scale + causal mask + online softmax ----
        const bool diag = (kb == qb);
        float mx0 = -1e30f, mx1 = -1e30f;
#pragma unroll
        for (int j = 0; j < 16; j++) {
            int kj = kb * 128 + j * 8 + cpair;
            float v0 = sacc[j][0] * 0.125f, v1 = sacc[j][1] * 0.125f;
            float v2 = sacc[j][2] * 0.125f, v3 = sacc[j][3] * 0.125f;
            if (diag) {
                if (kj > qi0)     v0 = -1e30f;
                if (kj + 1 > qi0) v1 = -1e30f;
                if (kj > qi1)     v2 = -1e30f;
                if (kj + 1 > qi1) v3 = -1e30f;
            }
            sacc[j][0] = v0; sacc[j][1] = v1; sacc[j][2] = v2; sacc[j][3] = v3;
            mx0 = fmaxf(mx0, fmaxf(v0, v1));
            mx1 = fmaxf(mx1, fmaxf(v2, v3));
        }
        mx0 = fmaxf(mx0, __shfl_xor_sync(0xffffffffu, mx0, 1));
        mx0 = fmaxf(mx0, __shfl_xor_sync(0xffffffffu, mx0, 2));
        mx1 = fmaxf(mx1, __shfl_xor_sync(0xffffffffu, mx1, 1));
        mx1 = fmaxf(mx1, __shfl_xor_sync(0xffffffffu, mx1, 2));
        float mn0 = fmaxf(m0, mx0), mn1 = fmaxf(m1, mx1);
        float c0 = __expf(m0 - mn0), c1 = __expf(m1 - mn1);
        float rs0 = 0.0f, rs1 = 0.0f;
#pragma unroll
        for (int j = 0; j < 16; j++) {
            float p0 = __expf(sacc[j][0] - mn0);
            float p1 = __expf(sacc[j][1] - mn0);
            float p2 = __expf(sacc[j][2] - mn1);
            float p3 = __expf(sacc[j][3] - mn1);
            sacc[j][0] = p0; sacc[j][1] = p1; sacc[j][2] = p2; sacc[j][3] = p3;
            rs0 += p0 + p1;
            rs1 += p2 + p3;
        }
        rs0 += __shfl_xor_sync(0xffffffffu, rs0, 1);
        rs0 += __shfl_xor_sync(0xffffffffu, rs0, 2);
        rs1 += __shfl_xor_sync(0xffffffffu, rs1, 1);
        rs1 += __shfl_xor_sync(0xffffffffu, rs1, 2);
        l0 = l0 * c0 + rs0;
        l1 = l1 * c1 + rs1;
        m0 = mn0; m1 = mn1;
#pragma unroll
        for (int e = 0; e < 8; e++) {
            oacc[e][0] *= c0; oacc[e][1] *= c0;
            oacc[e][2] *= c1; oacc[e][3] *= c1;
        }

        // ---- O += P @ V (3-pass, P frags packed from registers) ----
#pragma unroll
        for (int kt = 0; kt < 8; kt++) {
            uint32_t ph[4], pl[4];
            split_pack2(sacc[2 * kt][0],     sacc[2 * kt][1],     ph[0], pl[0]);
            split_pack2(sacc[2 * kt][2],     sacc[2 * kt][3],     ph[1], pl[1]);
            split_pack2(sacc[2 * kt + 1][0], sacc[2 * kt + 1][1], ph[2], pl[2]);
            split_pack2(sacc[2 * kt + 1][2], sacc[2 * kt + 1][3], ph[3], pl[3]);
#pragma unroll
            for (int e = 0; e < 4; e++) {
                uint32_t off = (uint32_t)((kt * 16 + vrow) * AT_RS) + vcol + e * 32;
                uint32_t vh[4], vl[4];
                ldsm4t(vh, VH + off);
                ldsm4t(vl, VL + off);
                mma_bf16(oacc[2 * e],     ph, vh[0], vh[1]);
                mma_bf16(oacc[2 * e + 1], ph, vh[2], vh[3]);
                mma_bf16(oacc[2 * e],     ph, vl[0], vl[1]);
                mma_bf16(oacc[2 * e + 1], ph, vl[2], vl[3]);
                mma_bf16(oacc[2 * e],     pl, vh[0], vh[1]);
                mma_bf16(oacc[2 * e + 1], pl, vh[2], vh[3]);
            }
        }

        // drain the in-flight cp.async group (if any) before buffer reuse
        cp_wait<0>();
        __syncthreads();
    }

    // ---- epilogue: normalize, split, write yh/yl ----
    const float i0 = 1.0f / l0, i1 = 1.0f / l1;
    const size_t row0 = (size_t)b * Tv + qb * 128 + wq + r0;
#pragma unroll
    for (int e = 0; e < 8; e++) {
        uint32_t h01, l01, h23, l23;
        split_pack2(oacc[e][0] * i0, oacc[e][1] * i0, h01, l01);
        split_pack2(oacc[e][2] * i1, oacc[e][3] * i1, h23, l23);
        size_t o0 = (row0 * Cv + coff + e * 8 + cpair) >> 1;
        size_t o1 = ((row0 + 8) * Cv + coff + e * 8 + cpair) >> 1;
        ((uint32_t*)yh)[o0] = h01;
        ((uint32_t*)yl)[o0] = l01;
        ((uint32_t*)yh)[o1] = h23;
        ((uint32_t*)yl)[o1] = l23;
    }
}

// ---------------------------------------------------------------------------
extern "C" void kernel_launch(void* const* d_in, const int* in_sizes, int n_in,
                              void* d_out, int out_size)
{
    const float* x      = (const float*)d_in[0];   // [4,2048,1024]
    const float* w_attn = (const float*)d_in[1];   // [1024,3072]
    const float* w_proj = (const float*)d_in[2];   // [1024,1024]
    float* out = (float*)d_out;                    // [4,2048,1024]

    void *p_qh, *p_ql, *p_xh, *p_xl, *p_yh, *p_yl, *p_wah, *p_wal, *p_wph, *p_wpl;
    cudaGetSymbolAddress(&p_qh, g_qkvh);
    cudaGetSymbolAddress(&p_ql, g_qkvl);
    cudaGetSymbolAddress(&p_xh, g_xh);
    cudaGetSymbolAddress(&p_xl, g_xl);
    cudaGetSymbolAddress(&p_yh, g_yh);
    cudaGetSymbolAddress(&p_yl, g_yl);
    cudaGetSymbolAddress(&p_wah, g_wah);
    cudaGetSymbolAddress(&p_wal, g_wal);
    cudaGetSymbolAddress(&p_wph, g_wph);
    cudaGetSymbolAddress(&p_wpl, g_wpl);

    cudaFuncSetAttribute(gemm_hmma_kernel<true>,
                         cudaFuncAttributeMaxDynamicSharedMemorySize, GH_SMEM);
    cudaFuncSetAttribute(gemm_hmma_kernel<false>,
                         cudaFuncAttributeMaxDynamicSharedMemorySize, GH_SMEM);
    cudaFuncSetAttribute(attn_tc_kernel,
                         cudaFuncAttributeMaxDynamicSharedMemorySize, AT_SMEM);

    // 1. split x into bf16 hi/lo
    split_kernel<<<1024, 256>>>(x, (__nv_bfloat16*)p_xh, (__nv_bfloat16*)p_xl,
                                (size_t)MROWS * Cv / 4);
    // 2. transpose+split weights
    splitT_kernel<<<dim3(NQKV / 32, Cv / 32), 256>>>(
        w_attn, (__nv_bfloat16*)p_wah, (__nv_bfloat16*)p_wal, Cv, NQKV);
    splitT_kernel<<<dim3(Cv / 32, Cv / 32), 256>>>(
        w_proj, (__nv_bfloat16*)p_wph, (__nv_bfloat16*)p_wpl, Cv, Cv);

    // 3. qkv = x @ w_attn -> split bf16 outputs directly
    gemm_hmma_kernel<true><<<dim3(NQKV / 128, MROWS / 128), 256, GH_SMEM>>>(
        (const __nv_bfloat16*)p_xh, (const __nv_bfloat16*)p_xl,
        (const __nv_bfloat16*)p_wah, (const __nv_bfloat16*)p_wal,
        nullptr, (__nv_bfloat16*)p_qh, (__nv_bfloat16*)p_ql,
        MROWS, NQKV, Cv);

    // 4. tensor-core attention -> yh/yl
    attn_tc_kernel<<<dim3(Tv / 128, Bv * Hv), 256, AT_SMEM>>>(
        (const __nv_bfloat16*)p_qh, (const __nv_bfloat16*)p_ql,
        (__nv_bfloat16*)p_yh, (__nv_bfloat16*)p_yl);

    // 5. out = y @ w_proj (fp32 output)
    gemm_hmma_kernel<false><<<dim3(Cv / 128, MROWS / 128), 256, GH_SMEM>>>(
        (const __nv_bfloat16*)p_yh, (const __nv_bfloat16*)p_yl,
        (const __nv_bfloat16*)p_wph, (const __nv_bfloat16*)p_wpl,
        out, nullptr, nullptr, MROWS, Cv, Cv);
}